// round 17
// baseline (speedup 1.0000x reference)
#include <cuda_runtime.h>
#include <cuda_bf16.h>
#include <cstdint>

#define B_ 8
#define N_ 2048
#define D_ 2048
#define E_ 256
#define M_TOTAL (B_*N_)   // 16384

// ---------------- scratch (device globals; no allocation allowed) ----------------
__device__ __nv_bfloat16 g_xb[M_TOTAL*D_];     // x in bf16 [M][D]
__device__ __nv_bfloat16 g_Wqb[D_*E_];         // W in bf16 [D][E]
__device__ __nv_bfloat16 g_Wkb[D_*E_];
__device__ __nv_bfloat16 g_Wvb[D_*E_];
__device__ __nv_bfloat16 g_Q[M_TOTAL*E_];
__device__ __nv_bfloat16 g_K[M_TOTAL*E_];
__device__ __nv_bfloat16 g_V[M_TOTAL*E_];
__device__ float g_xpart[16*B_*D_];            // partial column sums of x
__device__ float g_spart[8*B_*E_];             // partial S projections
__device__ float g_S[B_*E_];                   // (unused; kept for layout stability)

static __device__ __forceinline__ unsigned smem_u32(const void* p){
  return (unsigned)__cvta_generic_to_shared(p);
}
static __device__ __forceinline__ void cp16(unsigned dst, const void* src){
  asm volatile("cp.async.cg.shared.global [%0], [%1], 16;\n" :: "r"(dst), "l"(src));
}
static __device__ __forceinline__ void cp_commit(){
  asm volatile("cp.async.commit_group;\n");
}
template<int N> static __device__ __forceinline__ void cp_wait(){
  asm volatile("cp.async.wait_group %0;\n" :: "n"(N));
}
static __device__ __forceinline__ void bar_pair(int id){
  asm volatile("bar.sync %0, 64;\n" :: "r"(id) : "memory");
}
static __device__ __forceinline__ void ldsm_x4(unsigned* r, unsigned addr){
  asm volatile("ldmatrix.sync.aligned.m8n8.x4.shared.b16 {%0,%1,%2,%3}, [%4];\n"
    : "=r"(r[0]),"=r"(r[1]),"=r"(r[2]),"=r"(r[3]) : "r"(addr));
}
static __device__ __forceinline__ void ldsm_x4_t(unsigned* r, unsigned addr){
  asm volatile("ldmatrix.sync.aligned.m8n8.x4.trans.shared.b16 {%0,%1,%2,%3}, [%4];\n"
    : "=r"(r[0]),"=r"(r[1]),"=r"(r[2]),"=r"(r[3]) : "r"(addr));
}
static __device__ __forceinline__ void mma_bf16(float* c, const unsigned* a, unsigned b0, unsigned b1){
  asm volatile("mma.sync.aligned.m16n8k16.row.col.f32.bf16.bf16.f32 "
    "{%0,%1,%2,%3}, {%4,%5,%6,%7}, {%8,%9}, {%0,%1,%2,%3};\n"
    : "+f"(c[0]), "+f"(c[1]), "+f"(c[2]), "+f"(c[3])
    : "r"(a[0]), "r"(a[1]), "r"(a[2]), "r"(a[3]), "r"(b0), "r"(b1));
}

// ---------------- Kernel 1: merged staging (x cvt+colsums MLP-4, W cvt) ----------------
__global__ void k_cvtall(const float* __restrict__ x,
                         const float4* __restrict__ Wq, const float4* __restrict__ Wk,
                         const float4* __restrict__ Wv){
  int cta = blockIdx.x;
  if(cta < 256){
    int dblk = cta & 1, b = (cta>>1) & 7, ns = cta >> 4;
    int d = dblk*1024 + threadIdx.x*4;
    const float4* src = (const float4*)(x + (size_t)b*N_*D_ + (size_t)ns*128*D_ + d);
    __nv_bfloat162* dst = (__nv_bfloat162*)(g_xb + (size_t)b*N_*D_ + (size_t)ns*128*D_ + d);
    // 4 independent load streams (MLP=4) with 4 independent accumulators
    float4 sA = make_float4(0.f,0.f,0.f,0.f);
    float4 sB = sA, sC = sA, sD = sA;
    for(int n=0;n<128;n+=4){
      float4 v0 = src[(size_t)(n  )*(D_/4)];
      float4 v1 = src[(size_t)(n+1)*(D_/4)];
      float4 v2 = src[(size_t)(n+2)*(D_/4)];
      float4 v3 = src[(size_t)(n+3)*(D_/4)];
      dst[(size_t)(n  )*(D_/2)  ] = __floats2bfloat162_rn(v0.x,v0.y);
      dst[(size_t)(n  )*(D_/2)+1] = __floats2bfloat162_rn(v0.z,v0.w);
      dst[(size_t)(n+1)*(D_/2)  ] = __floats2bfloat162_rn(v1.x,v1.y);
      dst[(size_t)(n+1)*(D_/2)+1] = __floats2bfloat162_rn(v1.z,v1.w);
      dst[(size_t)(n+2)*(D_/2)  ] = __floats2bfloat162_rn(v2.x,v2.y);
      dst[(size_t)(n+2)*(D_/2)+1] = __floats2bfloat162_rn(v2.z,v2.w);
      dst[(size_t)(n+3)*(D_/2)  ] = __floats2bfloat162_rn(v3.x,v3.y);
      dst[(size_t)(n+3)*(D_/2)+1] = __floats2bfloat162_rn(v3.z,v3.w);
      sA.x+=v0.x; sA.y+=v0.y; sA.z+=v0.z; sA.w+=v0.w;
      sB.x+=v1.x; sB.y+=v1.y; sB.z+=v1.z; sB.w+=v1.w;
      sC.x+=v2.x; sC.y+=v2.y; sC.z+=v2.z; sC.w+=v2.w;
      sD.x+=v3.x; sD.y+=v3.y; sD.z+=v3.z; sD.w+=v3.w;
    }
    float4 s = make_float4((sA.x+sB.x)+(sC.x+sD.x), (sA.y+sB.y)+(sC.y+sD.y),
                           (sA.z+sB.z)+(sC.z+sD.z), (sA.w+sB.w)+(sC.w+sD.w));
    *(float4*)(g_xpart + ((size_t)(ns*B_+b))*D_ + d) = s;
  } else {
    int i2 = cta - 256;
    int z = i2 / 512, blk = i2 % 512;
    const float4* src = z==0 ? Wq : (z==1 ? Wk : Wv);
    __nv_bfloat162* dst = (__nv_bfloat162*)(z==0 ? g_Wqb : (z==1 ? g_Wkb : g_Wvb));
    int i = blk*256 + threadIdx.x;
    float4 v = src[i];
    dst[2*i  ] = __floats2bfloat162_rn(v.x, v.y);
    dst[2*i+1] = __floats2bfloat162_rn(v.z, v.w);
  }
}

// ---------------- Kernel 2: partial S projections (exact fp32) ----------------
__global__ void k_sproj1(const float* __restrict__ Wv){
  __shared__ float xs[256];
  int b = blockIdx.x, ds = blockIdx.y, e = threadIdx.x;
  {
    float s = 0.f;
    #pragma unroll
    for(int ns=0;ns<16;ns++) s += g_xpart[(size_t)(ns*B_ + b)*D_ + ds*256 + e];
    xs[e] = s;
  }
  __syncthreads();
  const float* Wp = Wv + (size_t)ds*256*E_ + e;
  float a0=0.f,a1=0.f,a2=0.f,a3=0.f;
  for(int d=0;d<256;d+=4){
    a0 += xs[d  ]*Wp[(size_t)(d  )*E_];
    a1 += xs[d+1]*Wp[(size_t)(d+1)*E_];
    a2 += xs[d+2]*Wp[(size_t)(d+2)*E_];
    a3 += xs[d+3]*Wp[(size_t)(d+3)*E_];
  }
  g_spart[(ds*B_+b)*E_ + e] = (a0+a1)+(a2+a3);
}

// ---------------- Kernel 3: QKV = xb @ W + b (R12 exact: CTA 128x256, BK=64, 8 warps) ----------------
#define QK_AS 144
#define QK_BS 528
#define QK_A_OFF 4096
#define QK_ASTAGE (128*QK_AS)            // 18432
#define QK_BSTAGE (64*QK_BS)             // 33792
#define QK_B_OFF (QK_A_OFF + 2*QK_ASTAGE)
#define QK_SMEM (QK_B_OFF + 2*QK_BSTAGE) // 108544

__global__ __launch_bounds__(256) void k_qkv(
    const float* __restrict__ bq, const float* __restrict__ bk, const float* __restrict__ bv)
{
  extern __shared__ char qs[];
  unsigned sb = smem_u32(qs);
  float* biass = (float*)qs;   // [3][256]

  int m0 = blockIdx.x*128;
  int tid = threadIdx.x;
  int w = tid>>5, lane = tid&31, g = lane>>2, tg = lane&3;
  int wm = w>>2, wn = w&3;   // warp tile 64(m) x 64(n)

  biass[tid]       = bq[tid];
  biass[tid + 256] = bk[tid];
  biass[tid + 512] = bv[tid];

  unsigned a_base = sb + QK_A_OFF;
  unsigned b_base = sb + QK_B_OFF;
  const __nv_bfloat16* xsrc = g_xb + (size_t)m0*D_;
  __syncthreads();

  for(int z=0; z<3; z++){
    const __nv_bfloat16* W = z==0 ? g_Wqb : (z==1 ? g_Wkb : g_Wvb);
    __nv_bfloat16* outp = z==0 ? g_Q : (z==1 ? g_K : g_V);
    const float* bs = biass + z*256;

    float acc[4][8][4];
    #pragma unroll
    for(int mt=0;mt<4;mt++)
      #pragma unroll
      for(int nc=0;nc<8;nc++)
        #pragma unroll
        for(int i=0;i<4;i++) acc[mt][nc][i]=0.f;

    // prologue: chunk 0 -> buffer 0
    {
      #pragma unroll
      for(int j=0;j<4;j++){   // A: 128 rows x 128B = 1024 cp16
        int idx = tid + 256*j; int row = idx>>3, c16 = idx&7;
        cp16(a_base + (unsigned)(row*QK_AS + c16*16), xsrc + (size_t)row*D_ + c16*8);
      }
      #pragma unroll
      for(int j=0;j<8;j++){   // B: 64 rows x 512B = 2048 cp16
        int idx = tid + 256*j; int row = idx>>5, c16 = idx&31;
        cp16(b_base + (unsigned)(row*QK_BS + c16*16), W + (size_t)row*E_ + c16*8);
      }
      cp_commit();
    }

    const int KT = D_/64;  // 32
    for(int kt=0; kt<KT; kt++){
      int cur = kt&1;
      if(kt+1 < KT){
        int nxt = cur^1;
        unsigned da = a_base + (unsigned)(nxt*QK_ASTAGE);
        unsigned db = b_base + (unsigned)(nxt*QK_BSTAGE);
        #pragma unroll
        for(int j=0;j<4;j++){
          int idx = tid + 256*j; int row = idx>>3, c16 = idx&7;
          cp16(da + (unsigned)(row*QK_AS + c16*16), xsrc + (size_t)row*D_ + (kt+1)*64 + c16*8);
        }
        #pragma unroll
        for(int j=0;j<8;j++){
          int idx = tid + 256*j; int row = idx>>5, c16 = idx&31;
          cp16(db + (unsigned)(row*QK_BS + c16*16), W + ((size_t)((kt+1)*64+row))*E_ + c16*8);
        }
        cp_commit();
        cp_wait<1>();
      } else {
        cp_wait<0>();
      }
      __syncthreads();

      unsigned ac = a_base + (unsigned)(cur*QK_ASTAGE);
      unsigned bc = b_base + (unsigned)(cur*QK_BSTAGE);
      #pragma unroll
      for(int kc=0;kc<4;kc++){
        unsigned a[4][4];
        #pragma unroll
        for(int mt=0;mt<4;mt++){
          int row = wm*64 + mt*16 + (lane&15);
          int col = kc*16 + (lane>>4)*8;
          ldsm_x4(a[mt], ac + (unsigned)(row*QK_AS + col*2));
        }
        #pragma unroll
        for(int nb=0;nb<4;nb++){
          unsigned r[4];
          int row = kc*16 + (lane&7) + ((lane>>3)&1)*8;
          int col = wn*64 + nb*16 + (lane>>4)*8;
          ldsm_x4_t(r, bc + (unsigned)(row*QK_BS + col*2));
          #pragma unroll
          for(int mt=0;mt<4;mt++){
            mma_bf16(acc[mt][2*nb  ], a[mt], r[0], r[1]);
            mma_bf16(acc[mt][2*nb+1], a[mt], r[2], r[3]);
          }
        }
      }
      __syncthreads();   // all warps done reading cur before it is overwritten
    }

    // epilogue: +bias, store bf16
    #pragma unroll
    for(int mt=0;mt<4;mt++){
      int r0 = m0 + wm*64 + mt*16 + g;
      #pragma unroll
      for(int nc=0;nc<8;nc++){
        int c = wn*64 + nc*8 + 2*tg;
        float b0 = bs[c], b1 = bs[c+1];
        *(__nv_bfloat162*)(outp + (size_t)r0*E_ + c) =
          __floats2bfloat162_rn(acc[mt][nc][0]+b0, acc[mt][nc][1]+b1);
        *(__nv_bfloat162*)(outp + (size_t)(r0+8)*E_ + c) =
          __floats2bfloat162_rn(acc[mt][nc][2]+b0, acc[mt][nc][3]+b1);
      }
    }
  }
}

// ---------------- Kernel 4: flash attention (R16 exact; S folded in) ----------------
#define A_BM 128
#define A_BN 64
#define QKST 264   // 528B rows for Q/K/V tiles
#define PST  72    // 144B rows for P
#define AQ_OFF 0
#define AK_OFF (128*QKST)
#define AV_OFF (AK_OFF + 2*64*QKST)
#define AP_OFF (AV_OFF + 2*64*QKST)
#define A_BF_TOT (AP_OFF + 128*PST)
#define A_SMEM (A_BF_TOT*2 + (128+256)*4)

__global__ __launch_bounds__(256,1) void k_attn(float* __restrict__ out,
                                                const float* __restrict__ bv){
  extern __shared__ __nv_bfloat16 sma[];
  float* Zs = (float*)(sma + A_BF_TOT);   // [128]
  float* Ss = Zs + 128;                   // [256]

  int bb = blockIdx.y;
  int n0 = blockIdx.x*A_BM;
  int tid = threadIdx.x;
  int w = tid>>5, lane = tid&31, g = lane>>2, tg = lane&3;
  int swm = w&3, swn = w>>2;   // scores: 32x32 warp tiles (4m x 2n); PV: 32x128

  if(tid < 128) Zs[tid] = 0.0f;
  // folded k_sproj2: S[e] = 2048*bv[e] + sum_ds g_spart (same ds order)
  {
    float s = 2048.0f*bv[tid];
    #pragma unroll
    for(int ds=0;ds<8;ds++) s += g_spart[(ds*B_+bb)*E_ + tid];
    Ss[tid] = s;
  }

  unsigned q_base = smem_u32(sma + AQ_OFF);
  unsigned k_base = smem_u32(sma + AK_OFF);
  unsigned v_base = smem_u32(sma + AV_OFF);
  unsigned p_base = smem_u32(sma + AP_OFF);

  // prologue: Q tile (128 rows) + KV block 0 in one group
  {
    const __nv_bfloat16* qsrc = g_Q + ((size_t)(bb*N_ + n0))*E_;
    const __nv_bfloat16* ksrc = g_K + ((size_t)bb*N_)*E_;
    const __nv_bfloat16* vsrc = g_V + ((size_t)bb*N_)*E_;
    #pragma unroll
    for(int j=0;j<16;j++){
      int idx = tid + 256*j; int row = idx>>5, c16 = idx&31;
      cp16(q_base + (unsigned)(row*528 + c16*16), qsrc + (size_t)row*E_ + c16*8);
    }
    #pragma unroll
    for(int j=0;j<8;j++){
      int idx = tid + 256*j; int row = idx>>5, c16 = idx&31;
      unsigned off = (unsigned)(row*528 + c16*16);
      size_t soff = (size_t)row*E_ + c16*8;
      cp16(k_base + off, ksrc + soff);
      cp16(v_base + off, vsrc + soff);
    }
    cp_commit();
  }

  float oacc[2][16][4];
  #pragma unroll
  for(int mt=0;mt<2;mt++)
    #pragma unroll
    for(int nc=0;nc<16;nc++)
      #pragma unroll
      for(int i=0;i<4;i++) oacc[mt][nc][i]=0.f;

  const int KB = N_/A_BN;  // 32
  for(int kb=0; kb<KB; kb++){
    int cur = kb&1;

    cp_wait<0>();      // drain KV(kb) group (committed at kb-1, or prologue)
    __syncthreads();   // KV(kb) visible; ALL warps done PV(kb-1) -> safe to overwrite nxt buffer

    if(kb+1 < KB){
      int nxt = cur^1;
      unsigned dk = k_base + (unsigned)(nxt*64*QKST*2);
      unsigned dv = v_base + (unsigned)(nxt*64*QKST*2);
      const __nv_bfloat16* ksrc = g_K + ((size_t)(bb*N_ + (kb+1)*A_BN))*E_;
      const __nv_bfloat16* vsrc = g_V + ((size_t)(bb*N_ + (kb+1)*A_BN))*E_;
      #pragma unroll
      for(int j=0;j<8;j++){
        int idx = tid + 256*j; int row = idx>>5, c16 = idx&31;
        unsigned off = (unsigned)(row*528 + c16*16);
        size_t soff = (size_t)row*E_ + c16*8;
        cp16(dk + off, ksrc + soff);
        cp16(dv + off, vsrc + soff);
      }
      cp_commit();
    }

    unsigned kc_base = k_base + (unsigned)(cur*64*QKST*2);
    unsigned vc_base = v_base + (unsigned)(cur*64*QKST*2);

    // ---- scores: 128x64, warp tile 32x32 ----
    float sc[2][4][4];
    #pragma unroll
    for(int mt=0;mt<2;mt++)
      #pragma unroll
      for(int nc=0;nc<4;nc++)
        #pragma unroll
        for(int i=0;i<4;i++) sc[mt][nc][i]=0.f;

    #pragma unroll
    for(int kc=0;kc<16;kc++){
      unsigned a[2][4];
      #pragma unroll
      for(int mt=0;mt<2;mt++){
        int row = swm*32 + mt*16 + (lane&15);
        int col = kc*16 + (lane>>4)*8;
        ldsm_x4(a[mt], q_base + (unsigned)(row*528 + col*2));
      }
      #pragma unroll
      for(int nb=0;nb<2;nb++){
        unsigned r[4];
        int row = swn*32 + nb*16 + (lane&15);
        int col = kc*16 + (lane>>4)*8;
        ldsm_x4(r, kc_base + (unsigned)(row*528 + col*2));
        #pragma unroll
        for(int mt=0;mt<2;mt++){
          mma_bf16(sc[mt][2*nb  ], a[mt], r[0], r[2]);
          mma_bf16(sc[mt][2*nb+1], a[mt], r[1], r[3]);
        }
      }
    }

    // ---- p = expm1(sigmoid(s)/16); Z row sums; store P bf16 ----
    #pragma unroll
    for(int mt=0;mt<2;mt++){
      float zlo=0.f, zhi=0.f;
      #pragma unroll
      for(int nc=0;nc<4;nc++){
        #pragma unroll
        for(int i=0;i<4;i++){
          float s = sc[mt][nc][i];
          float sig = __fdividef(1.0f, 1.0f + __expf(-s));
          float gg = 0.0625f * sig;
          sc[mt][nc][i] = gg*fmaf(gg, fmaf(gg, fmaf(gg, 0.041666668f, 0.16666667f), 0.5f), 1.0f);
        }
        zlo += sc[mt][nc][0]+sc[mt][nc][1];
        zhi += sc[mt][nc][2]+sc[mt][nc][3];
      }
      zlo += __shfl_xor_sync(0xffffffffu, zlo, 1);
      zlo += __shfl_xor_sync(0xffffffffu, zlo, 2);
      zhi += __shfl_xor_sync(0xffffffffu, zhi, 1);
      zhi += __shfl_xor_sync(0xffffffffu, zhi, 2);
      if(tg==0){
        atomicAdd(&Zs[swm*32+mt*16+g],   zlo);
        atomicAdd(&Zs[swm*32+mt*16+g+8], zhi);
      }
      #pragma unroll
      for(int nc=0;nc<4;nc++){
        int c = swn*32 + nc*8 + 2*tg;
        *(__nv_bfloat162*)((char*)sma + AP_OFF*2 + (swm*32+mt*16+g  )*144 + c*2) =
          __floats2bfloat162_rn(sc[mt][nc][0], sc[mt][nc][1]);
        *(__nv_bfloat162*)((char*)sma + AP_OFF*2 + (swm*32+mt*16+g+8)*144 + c*2) =
          __floats2bfloat162_rn(sc[mt][nc][2], sc[mt][nc][3]);
      }
    }
    // pair barrier: P rows [swm*32, swm*32+32) produced by warps {swm, swm+4}
    bar_pair(1+swm);

    // ---- out += P @ V : P 128x64, V 64x256, warp tile 32x128 ----
    #pragma unroll
    for(int kc=0;kc<4;kc++){
      unsigned pa[2][4];
      #pragma unroll
      for(int mt=0;mt<2;mt++){
        int row = swm*32 + mt*16 + (lane&15);
        int col = kc*16 + (lane>>4)*8;
        ldsm_x4(pa[mt], p_base + (unsigned)(row*144 + col*2));
      }
      #pragma unroll
      for(int nb=0;nb<8;nb++){
        unsigned r[4];
        int row = kc*16 + (lane&7) + ((lane>>3)&1)*8;
        int col = swn*128 + nb*16 + (lane>>4)*8;
        ldsm_x4_t(r, vc_base + (unsigned)(row*528 + col*2));
        #pragma unroll
        for(int mt=0;mt<2;mt++){
          mma_bf16(oacc[mt][2*nb  ], pa[mt], r[0], r[1]);
          mma_bf16(oacc[mt][2*nb+1], pa[mt], r[2], r[3]);
        }
      }
    }
    // no trailing barrier: loop-top __syncthreads orders P-reads before next
    // P-writes, and the KV prefetch is issued after that sync too.
  }

  // epilogue: out = (S + acc) / (2048 + Z)
  #pragma unroll
  for(int mt=0;mt<2;mt++){
    int r = swm*32 + mt*16 + g;
    float rz0 = __fdividef(1.0f, 2048.0f + Zs[r]);
    float rz1 = __fdividef(1.0f, 2048.0f + Zs[r+8]);
    #pragma unroll
    for(int nc=0;nc<16;nc++){
      int c = swn*128 + nc*8 + 2*tg;
      float s0 = Ss[c], s1 = Ss[c+1];
      float2 y0 = make_float2((s0+oacc[mt][nc][0])*rz0, (s1+oacc[mt][nc][1])*rz0);
      float2 y1 = make_float2((s0+oacc[mt][nc][2])*rz1, (s1+oacc[mt][nc][3])*rz1);
      *(float2*)(out + ((size_t)(bb*N_ + n0 + r  ))*E_ + c) = y0;
      *(float2*)(out + ((size_t)(bb*N_ + n0 + r+8))*E_ + c) = y1;
    }
  }
}

extern "C" void kernel_launch(void* const* d_in, const int* in_sizes, int n_in,
                              void* d_out, int out_size){
  const float* x  = (const float*)d_in[0];
  const float* Wq = (const float*)d_in[1];
  const float* bq = (const float*)d_in[2];
  const float* Wk = (const float*)d_in[3];
  const float* bk = (const float*)d_in[4];
  const float* Wv = (const float*)d_in[5];
  const float* bv = (const float*)d_in[6];
  float* out = (float*)d_out;

  cudaFuncSetAttribute(k_qkv,  cudaFuncAttributeMaxDynamicSharedMemorySize, QK_SMEM);
  cudaFuncSetAttribute(k_attn, cudaFuncAttributeMaxDynamicSharedMemorySize, A_SMEM);

  // 1) merged staging: x->bf16 (+ column sums, MLP-4) and W->bf16
  k_cvtall<<<256 + 3*512, 256>>>(x, (const float4*)Wq, (const float4*)Wk, (const float4*)Wv);

  // 2) partial S projections (final reduction folded into k_attn)
  k_sproj1<<<dim3(B_, 8), 256>>>(Wv);

  // 3) bf16 QKV projection (R12 plateau config)
  k_qkv<<<dim3(M_TOTAL/128, 1, 1), 256, QK_SMEM>>>(bq, bk, bv);

  // 4) bf16 flash attention
  k_attn<<<dim3(N_/A_BM, B_), 256, A_SMEM>>>(out, bv);
}